// round 15
// baseline (speedup 1.0000x reference)
#include <cuda_runtime.h>
#include <cstdint>

// Problem constants
#define Bn  1024
#define Sn  128
#define En  256
#define Hn  8
#define Dn  64
#define HDn 512

// Scratch (tf32 bit patterns in float arrays).
// g_Xt: [b][chunk c:8][frag f:32][lane:32][word j:4] (proj A fragments)
// g_Wt: [bx:16][chunk c:8][frag f:32][lane:32][word j:4] (proj B fragments)
// g_Q : per (b,h) 8192-u32 blob [mb:8][ks_d:8][lane:32][j:4]  (attn A-frag)
//       j: {(r,k),(r+8,k),(r,k+4),(r+8,k+4)}, r=16mb+g', k=8ks+tg'
// g_K : per (b,h) blob [ks_d:8][p_s:8][lane:32][j:4]          (attn B-frag)
//       j: {(n,k),(n,k+4),(n+8,k),(n+8,k+4)}, n=16p+g' (s-dim), k=8ks+tg' (d)
// g_V : per (b,h) blob [ks_s:16][p_d:4][lane:32][j:4]         (attn B-frag)
//       j as K but n=d-dim, k=s-dim
__device__ float g_Q[67108864];
__device__ float g_K[67108864];
__device__ float g_V[67108864];
__device__ float g_Xt[33554432];          // 1024*8*4096
__device__ float g_Wt[524288];            // 16*8*4096

// ---------------------------------------------------------------------------
// Helpers. tcgen05 unusable (harness PTX target sm_103, no 'a' suffix) -> the
// tensor path is arch-portable mma.sync (HMMA on sm_103a).
// ---------------------------------------------------------------------------
__device__ __forceinline__ uint32_t smem_u32(const void* p) {
    uint32_t a;
    asm("{ .reg .u64 t; cvta.to.shared.u64 t, %1; cvt.u32.u64 %0, t; }"
        : "=r"(a) : "l"(p));
    return a;
}
__device__ __forceinline__ uint32_t f2tf32(float x) {
    uint32_t r;
    asm("cvt.rna.tf32.f32 %0, %1;" : "=r"(r) : "f"(x));
    return r;
}
__device__ __forceinline__ void mma_tf32(float* c,
                                         const uint32_t* a,
                                         const uint32_t* b) {
    asm volatile(
        "mma.sync.aligned.m16n8k8.row.col.f32.tf32.tf32.f32 "
        "{%0,%1,%2,%3}, {%4,%5,%6,%7}, {%8,%9}, {%0,%1,%2,%3};"
        : "+f"(c[0]), "+f"(c[1]), "+f"(c[2]), "+f"(c[3])
        : "r"(a[0]), "r"(a[1]), "r"(a[2]), "r"(a[3]),
          "r"(b[0]), "r"(b[1]));
}
__device__ __forceinline__ void cpa16(uint32_t saddr, const void* g) {
    asm volatile("cp.async.cg.shared.global [%0], [%1], 16;"
                 :: "r"(saddr), "l"(g) : "memory");
}
#define CP_COMMIT() asm volatile("cp.async.commit_group;" ::: "memory")
#define CP_WAIT(n)  asm volatile("cp.async.wait_group %0;" :: "n"(n) : "memory")

// =============================================================================
// Kernel 0a: convert X -> tf32 bits, permuted into proj fragment layout.
// =============================================================================
__global__ void xconv_kernel(const float* __restrict__ X)
{
    const int c = blockIdx.x;
    const int b = blockIdx.y;
    const float* src = X + (size_t)b * Sn * En;
    uint4* dst = (uint4*)((uint32_t*)g_Xt + ((size_t)b * 8 + c) * 4096);

#pragma unroll
    for (int i = 0; i < 4; ++i) {
        const int o  = threadIdx.x + i * 256;   // 0..1023
        const int f  = o >> 5;
        const int l  = o & 31;
        const int mi = f >> 2, ks = f & 3;
        const int g  = l >> 2, tg = l & 3;
        const int m  = mi * 16 + g;
        const int k  = c * 32 + ks * 8 + tg;
        uint4 v;
        v.x = f2tf32(src[(size_t)m * En + k]);
        v.y = f2tf32(src[(size_t)(m + 8) * En + k]);
        v.z = f2tf32(src[(size_t)m * En + k + 4]);
        v.w = f2tf32(src[(size_t)(m + 8) * En + k + 4]);
        dst[o] = v;
    }
}

// =============================================================================
// Kernel 0b: weight transpose + convert + proj fragment permute.
// =============================================================================
__global__ void wtrans_kernel(const float* __restrict__ Wq,
                              const float* __restrict__ Wk,
                              const float* __restrict__ Wv,
                              const float* __restrict__ Wr)
{
    const int c  = blockIdx.x;
    const int bx = blockIdx.y;
    const int w  = bx >> 2;
    const int ncol0 = (bx & 3) * 128;
    const float* W = (w == 0) ? Wq : (w == 1) ? Wk : (w == 2) ? Wv : Wr;
    uint4* dst = (uint4*)((uint32_t*)g_Wt + ((size_t)bx * 8 + c) * 4096);

#pragma unroll
    for (int i = 0; i < 4; ++i) {
        const int o  = threadIdx.x + i * 256;
        const int f  = o >> 5;
        const int l  = o & 31;
        const int pb = f >> 2, ks = f & 3;
        const int g  = l >> 2, tg = l & 3;
        const int n0 = pb * 16 + g;
        const int k  = c * 32 + ks * 8 + tg;
        uint4 v;
        v.x = f2tf32(W[(size_t)k * HDn + ncol0 + n0]);
        v.y = f2tf32(W[(size_t)(k + 4) * HDn + ncol0 + n0]);
        v.z = f2tf32(W[(size_t)k * HDn + ncol0 + n0 + 8]);
        v.w = f2tf32(W[(size_t)(k + 4) * HDn + ncol0 + n0 + 8]);
        dst[o] = v;
    }
}

// =============================================================================
// Kernel 1: tf32 mma.sync projection GEMM (round-13 structure; epilogue now
// writes Q/K/V in attn-fragment-major blobs). grid (16,1024), 128 threads,
// warp tile 64x64, 3-stage cp.async, one sync per chunk, 2 CTAs/SM.
// Same values, same accumulation order -> bit-identical results.
// =============================================================================
constexpr int CHUNK_U = 4096;                // u32 per matrix per chunk (16 KB)
constexpr int SLOT_U  = 2 * CHUNK_U;         // 8192 u32 = 32 KB

__global__ __launch_bounds__(128)
void proj_mma(float* __restrict__ out)
{
    extern __shared__ uint32_t sm[];
    const uint32_t sb = smem_u32(sm);

    const int tid  = threadIdx.x;
    const int wid  = tid >> 5;      // 0..3
    const int lane = tid & 31;
    const int bx   = blockIdx.x;
    const int b    = blockIdx.y;
    const int w    = bx >> 2;
    const int ncol0 = (bx & 3) * 128;
    const int g    = lane >> 2;
    const int tg   = lane & 3;

    const int wm = wid >> 1;        // 0..1 -> m base wm*64
    const int wn = wid & 1;         // 0..1 -> n base wn*64

    const uint4* Ag = (const uint4*)((const uint32_t*)g_Xt + (size_t)b * 8 * 4096);
    const uint4* Bg = (const uint4*)((const uint32_t*)g_Wt + (size_t)bx * 8 * 4096);

    auto issue = [&](int c) {
        const int slot = c % 3;
        const uint32_t a_s = sb + (uint32_t)slot * SLOT_U * 4;
        const uint32_t b_s = a_s + CHUNK_U * 4;
        const uint4* ag = Ag + c * 1024;
        const uint4* bg = Bg + c * 1024;
#pragma unroll
        for (int i = 0; i < 8; ++i) {
            const int o = tid + i * 128;
            cpa16(a_s + o * 16, ag + o);
            cpa16(b_s + o * 16, bg + o);
        }
        CP_COMMIT();
    };

    issue(0);
    issue(1);

    float acc[4][8][4];
#pragma unroll
    for (int mt = 0; mt < 4; ++mt)
#pragma unroll
        for (int nt = 0; nt < 8; ++nt)
#pragma unroll
            for (int j = 0; j < 4; ++j) acc[mt][nt][j] = 0.f;

#pragma unroll 1
    for (int c = 0; c < 8; ++c) {
        const int slot = c % 3;
        if (c < 7) { CP_WAIT(1); } else { CP_WAIT(0); }
        __syncthreads();
        if (c < 6) issue(c + 2);

        const uint32_t* SA = sm + slot * SLOT_U;
        const uint32_t* SB = SA + CHUNK_U;
#pragma unroll
        for (int ks = 0; ks < 4; ++ks) {
            uint32_t af[4][4], bf[8][2];
#pragma unroll
            for (int mt = 0; mt < 4; ++mt) {
                uint4 a = *(const uint4*)(SA + (((wm * 4 + mt) * 4 + ks) * 32 + lane) * 4);
                af[mt][0] = a.x; af[mt][1] = a.y; af[mt][2] = a.z; af[mt][3] = a.w;
            }
#pragma unroll
            for (int p = 0; p < 4; ++p) {
                uint4 bq = *(const uint4*)(SB + (((wn * 4 + p) * 4 + ks) * 32 + lane) * 4);
                bf[2 * p][0]     = bq.x; bf[2 * p][1]     = bq.y;
                bf[2 * p + 1][0] = bq.z; bf[2 * p + 1][1] = bq.w;
            }
#pragma unroll
            for (int mt = 0; mt < 4; ++mt)
#pragma unroll
                for (int nt = 0; nt < 8; ++nt)
                    mma_tf32(acc[mt][nt], af[mt], bf[nt]);
        }
    }

    // Epilogue: Q/K/V into attn-fragment blobs (tf32 bits), R row-major fp32.
    const int hh = (ncol0 + wn * 64) >> 6;          // head for this warp half
    uint32_t* blobQ = (uint32_t*)g_Q + (size_t)(b * Hn + hh) * 8192;
    uint32_t* blobK = (uint32_t*)g_K + (size_t)(b * Hn + hh) * 8192;
    uint32_t* blobV = (uint32_t*)g_V + (size_t)(b * Hn + hh) * 8192;

#pragma unroll
    for (int mt = 0; mt < 4; ++mt) {
        const int row = wm * 64 + mt * 16 + g;      // s row (for R)
#pragma unroll
        for (int nt = 0; nt < 8; ++nt) {
            const float* a = acc[mt][nt];
            if (w == 0) {
                // Q: A-frag [mb:8][ks:8][lane][j], j:{(r,k),(r+8,k),(r,k+4),(r+8,k+4)}
                uint32_t* blk = blobQ + ((wm * 4 + mt) * 8 + nt) * 128;
                const int j0 = (tg >= 2) ? 2 : 0;
                const int l0 = g * 4 + ((2 * tg) & 3);
                const int l1 = g * 4 + ((2 * tg + 1) & 3);
                *(uint2*)(blk + l0 * 4 + j0) = make_uint2(f2tf32(a[0]), f2tf32(a[2]));
                *(uint2*)(blk + l1 * 4 + j0) = make_uint2(f2tf32(a[1]), f2tf32(a[3]));
            } else if (w == 1) {
                // K: B-frag [ks_d:8][p_s:8][lane][j], j:{(n,k),(n,k+4),(n+8,k),(n+8,k+4)}
                uint32_t* blk = blobK + (nt * 8 + (wm * 4 + mt)) * 128;
                const int jd = (tg >= 2) ? 1 : 0;
                const int l0 = g * 4 + ((2 * tg) & 3);
                const int l1 = g * 4 + ((2 * tg + 1) & 3);
                blk[l0 * 4 + jd]     = f2tf32(a[0]);
                blk[l1 * 4 + jd]     = f2tf32(a[1]);
                blk[l0 * 4 + jd + 2] = f2tf32(a[2]);
                blk[l1 * 4 + jd + 2] = f2tf32(a[3]);
            } else if (w == 2) {
                // V: B-frag [ks_s:16][p_d:4][lane][j]; k = s-dim, n = d-dim
                const int ks2 = wm * 8 + mt * 2;
                const int p   = nt >> 1;
                const int jv  = ((nt & 1) ? 2 : 0) + ((g & 4) ? 1 : 0);
                uint32_t* blkA = blobV + (ks2 * 4 + p) * 128;
                uint32_t* blkB = blkA + 512;        // ks2+1
                const int l0 = (2 * tg) * 4 + (g & 3);
                const int l1 = (2 * tg + 1) * 4 + (g & 3);
                blkA[l0 * 4 + jv] = f2tf32(a[0]);
                blkA[l1 * 4 + jv] = f2tf32(a[1]);
                blkB[l0 * 4 + jv] = f2tf32(a[2]);
                blkB[l1 * 4 + jv] = f2tf32(a[3]);
            } else {
                const int nw = ncol0 + wn * 64 + nt * 8 + tg * 2;
                float* dst = out + ((size_t)b * Sn + row) * HDn + nw;
                *(float2*)dst             = make_float2(a[0], a[1]);
                *(float2*)(dst + 8 * HDn) = make_float2(a[2], a[3]);
            }
        }
    }
}

// =============================================================================
// Kernel 2: tf32 mma.sync attention with fragment-major Q/K/V.
// One CTA per (b,h), 256 threads, 8 warps. QK: 8 af.128 + 64 bf.128 per
// thread; PV: 64 af.32 (P) + 64 bf.128. All fragment LDS.128 conflict-free.
// Smem: SQf[8192] SKf[8192] pad[512] SVf[8192]; SP[128x132]=16896 overlays
// SQf+SKf+pad exactly. Accumulation order unchanged -> bit-identical.
// =============================================================================
constexpr int SK_OFF = 8192;
constexpr int SV_OFF = 16896;
constexpr int ATTN_U = 25088;                 // 100352 B
constexpr int PPs = 132;

__global__ __launch_bounds__(256)
void attn_mma(float* __restrict__ out)
{
    extern __shared__ uint32_t smu[];
    uint32_t* SP = smu;                       // overlays SQf+SKf+pad

    const int tid  = threadIdx.x;
    const int wid  = tid >> 5;
    const int lane = tid & 31;
    const int g    = lane >> 2;
    const int tg   = lane & 3;
    const int h = blockIdx.x;
    const int b = (Bn - 1) - blockIdx.y;      // reversed: reuse proj's L2 tail

    const size_t base = (size_t)(b * Hn + h) * 8192;
    const uint4* Qg = (const uint4*)((const uint32_t*)g_Q + base);
    const uint4* Kg = (const uint4*)((const uint32_t*)g_K + base);
    const uint4* Vg = (const uint4*)((const uint32_t*)g_V + base);

    const uint32_t sb = smem_u32(smu);

    // ---- stage Q,K,V fragment blobs (raw bytes) via cp.async ----
#pragma unroll
    for (int i = 0; i < 8; ++i) {
        const int o = tid + i * 256;          // 0..2047 uint4s
        cpa16(sb + o * 16,               Qg + o);
        cpa16(sb + SK_OFF * 4 + o * 16,  Kg + o);
        cpa16(sb + SV_OFF * 4 + o * 16,  Vg + o);
    }
    CP_COMMIT();
    CP_WAIT(0);
    __syncthreads();

    // ---- S = Q K^T : warp owns rows wid*16..+16, all 128 cols ----
    float acc[16][4];
#pragma unroll
    for (int nt = 0; nt < 16; ++nt)
#pragma unroll
        for (int j = 0; j < 4; ++j) acc[nt][j] = 0.f;

#pragma unroll
    for (int ks = 0; ks < 8; ++ks) {
        uint4 aq = *(const uint4*)(smu + ((wid * 8 + ks) * 32 + lane) * 4);
        uint32_t af[4] = { aq.x, aq.y, aq.z, aq.w };
#pragma unroll
        for (int p = 0; p < 8; ++p) {
            uint4 bq = *(const uint4*)(smu + SK_OFF + ((ks * 8 + p) * 32 + lane) * 4);
            uint32_t bf0[2] = { bq.x, bq.y };
            uint32_t bf1[2] = { bq.z, bq.w };
            mma_tf32(acc[2 * p],     af, bf0);
            mma_tf32(acc[2 * p + 1], af, bf1);
        }
    }

    // ---- softmax rows r0 = wid*16+g, r1 = r0+8 (quad-local shfl) ----
    const int r0 = wid * 16 + g;
    float m0 = -1e30f, m1 = -1e30f;
#pragma unroll
    for (int nt = 0; nt < 16; ++nt) {
        m0 = fmaxf(m0, fmaxf(acc[nt][0], acc[nt][1]));
        m1 = fmaxf(m1, fmaxf(acc[nt][2], acc[nt][3]));
    }
#pragma unroll
    for (int off = 2; off >= 1; off >>= 1) {
        m0 = fmaxf(m0, __shfl_xor_sync(0xffffffffu, m0, off));
        m1 = fmaxf(m1, __shfl_xor_sync(0xffffffffu, m1, off));
    }
    float s0 = 0.f, s1 = 0.f;
#pragma unroll
    for (int nt = 0; nt < 16; ++nt) {
        acc[nt][0] = __expf(acc[nt][0] - m0);
        acc[nt][1] = __expf(acc[nt][1] - m0);
        acc[nt][2] = __expf(acc[nt][2] - m1);
        acc[nt][3] = __expf(acc[nt][3] - m1);
        s0 += acc[nt][0] + acc[nt][1];
        s1 += acc[nt][2] + acc[nt][3];
    }
#pragma unroll
    for (int off = 2; off >= 1; off >>= 1) {
        s0 += __shfl_xor_sync(0xffffffffu, s0, off);
        s1 += __shfl_xor_sync(0xffffffffu, s1, off);
    }
    const float inv0 = 1.0f / s0;
    const float inv1 = 1.0f / s1;

    // ---- prefetch residual (hides LDG latency under the PV loop) ----
    float* op = out + ((size_t)b * Sn) * HDn + h * Dn;
    float2 res0[8], res1[8];
#pragma unroll
    for (int nt = 0; nt < 8; ++nt) {
        const int d = nt * 8 + tg * 2;
        res0[nt] = *(const float2*)(op + (size_t)r0 * HDn + d);
        res1[nt] = *(const float2*)(op + (size_t)(r0 + 8) * HDn + d);
    }

    __syncthreads();   // all warps done reading SQf/SKf before SP overlays them

#pragma unroll
    for (int nt = 0; nt < 16; ++nt) {
        const int cl = nt * 8 + tg * 2;
        *(uint2*)&SP[r0 * PPs + cl] =
            make_uint2(f2tf32(acc[nt][0]), f2tf32(acc[nt][1]));
        *(uint2*)&SP[(r0 + 8) * PPs + cl] =
            make_uint2(f2tf32(acc[nt][2]), f2tf32(acc[nt][3]));
    }
    __syncthreads();

    // ---- O = P V ----
    float oacc[8][4];
#pragma unroll
    for (int nt = 0; nt < 8; ++nt)
#pragma unroll
        for (int j = 0; j < 4; ++j) oacc[nt][j] = 0.f;

    const uint32_t* Ap = SP + (wid * 16 + g) * PPs;
#pragma unroll
    for (int ks2 = 0; ks2 < 16; ++ks2) {
        const int k0 = ks2 * 8;
        uint32_t af[4];
        af[0] = Ap[k0 + tg];
        af[1] = Ap[8 * PPs + k0 + tg];
        af[2] = Ap[k0 + tg + 4];
        af[3] = Ap[8 * PPs + k0 + tg + 4];
#pragma unroll
        for (int p = 0; p < 4; ++p) {
            uint4 bq = *(const uint4*)(smu + SV_OFF + ((ks2 * 4 + p) * 32 + lane) * 4);
            uint32_t bf0[2] = { bq.x, bq.y };
            uint32_t bf1[2] = { bq.z, bq.w };
            mma_tf32(oacc[2 * p],     af, bf0);
            mma_tf32(oacc[2 * p + 1], af, bf1);
        }
    }

    // ---- epilogue: normalize, +residual (prefetched), ReLU ----
#pragma unroll
    for (int nt = 0; nt < 8; ++nt) {
        const int d = nt * 8 + tg * 2;
        float x0 = res0[nt].x + oacc[nt][0] * inv0;
        float x1 = res0[nt].y + oacc[nt][1] * inv0;
        float x2 = res1[nt].x + oacc[nt][2] * inv1;
        float x3 = res1[nt].y + oacc[nt][3] * inv1;
        *(float2*)(op + (size_t)r0 * HDn + d) =
            make_float2(fmaxf(x0, 0.f), fmaxf(x1, 0.f));
        *(float2*)(op + (size_t)(r0 + 8) * HDn + d) =
            make_float2(fmaxf(x2, 0.f), fmaxf(x3, 0.f));
    }
}

// =============================================================================
extern "C" void kernel_launch(void* const* d_in, const int* in_sizes, int n_in,
                              void* d_out, int out_size)
{
    const float* X  = (const float*)d_in[0];
    const float* Wq = (const float*)d_in[1];
    const float* Wk = (const float*)d_in[2];
    const float* Wv = (const float*)d_in[3];
    const float* Wr = (const float*)d_in[4];
    float* out = (float*)d_out;

    const int proj_smem = 3 * SLOT_U * (int)sizeof(uint32_t);   // 98304
    const int attn_smem = ATTN_U * (int)sizeof(uint32_t);       // 100352
    cudaFuncSetAttribute(proj_mma,
                         cudaFuncAttributeMaxDynamicSharedMemorySize, proj_smem);
    cudaFuncSetAttribute(attn_mma,
                         cudaFuncAttributeMaxDynamicSharedMemorySize, attn_smem);

    xconv_kernel<<<dim3(8, 1024), 256>>>(X);
    wtrans_kernel<<<dim3(8, 16), 256>>>(Wq, Wk, Wv, Wr);
    proj_mma<<<dim3(16, 1024), 128, proj_smem>>>(out);
    attn_mma<<<dim3(8, 1024), 256, attn_smem>>>(out);
}